// round 1
// baseline (speedup 1.0000x reference)
#include <cuda_runtime.h>
#include <math.h>

#define NB 8
#define CC 256
#define TT 120
#define VVC 25
#define PP (NB*TT*VVC)   // 24000 points
#define TV (TT*VVC)      // 3000
#define HH 8
#define HD 32
#define LLN 125
#define EPSV 1e-5f

// Scratch (device globals; no allocation anywhere)
__device__ __align__(16) float g_qkv[PP*768];    // (p, 768) cols = h*96 + s*32 + d
__device__ __align__(16) float g_ao[PP*256];     // mean-over-W attention out, (p, h*32+d)
__device__ __align__(16) float g_inter[PP*256];  // bn1 output, point-major
__device__ __align__(16) float g_h1[PP*256];     // ffn mid, point-major

// ---------------------------------------------------------------------------
// Generic 64-point x 256-col GEMM with K=256, fused epilogues.
// MODE 0: qkv    : A = x (NCHW gather), W=(in,out) ld=768, out -> g_qkv (grid.y = section)
// MODE 1: proj   : A = g_ao, W=w_out (in,out), epi: +b_out +x bn1 -> g_inter
// MODE 2: ffn1   : A = g_inter, W=ffn_w1 (out,in), epi: mish bn -> g_h1
// MODE 3: ffn2   : A = g_h1, W=ffn_w2 (out,in), epi: +g_inter bn2 -> out (NCHW scatter)
// ---------------------------------------------------------------------------
template<int MODE>
__global__ __launch_bounds__(256)
void gemm_kernel(const float* __restrict__ Aext, const float* __restrict__ Wm,
                 const float* __restrict__ bias, const float* __restrict__ res,
                 const float* __restrict__ bg, const float* __restrict__ bb,
                 const float* __restrict__ bm, const float* __restrict__ bv,
                 float* __restrict__ outp)
{
    __shared__ float A_s[64*33];        // [pl*33 + cl]
    __shared__ float W_s[32*260];       // [cl*260 + j]

    const int tid = threadIdx.x;
    const int cg = tid & 31;            // 32 col-groups * 8 cols
    const int pg = tid >> 5;            // 8 point-groups * 8 points
    const int p0 = blockIdx.x * 64;
    const int jb = (MODE == 0) ? (int)blockIdx.y * 256 : 0;

    const float* A;
    if constexpr (MODE == 0) A = Aext;
    else if constexpr (MODE == 1) A = g_ao;
    else if constexpr (MODE == 2) A = g_inter;
    else A = g_h1;

    float acc[8][8];
    #pragma unroll
    for (int i = 0; i < 8; ++i)
        #pragma unroll
        for (int j = 0; j < 8; ++j) acc[i][j] = 0.f;

    for (int kt = 0; kt < 8; ++kt) {
        const int c0 = kt * 32;
        // ---- load A tile (64 points x 32 channels) ----
        if constexpr (MODE == 0) {
            // gather from x (N,C,T,V): coalesced along flat (t,v)
            #pragma unroll
            for (int it = 0; it < 8; ++it) {
                int lin = it * 256 + tid;
                int pl = lin & 63, cl = lin >> 6;
                int p = p0 + pl;
                int n = p / TV, r = p - n * TV;
                A_s[pl*33 + cl] = A[(n*CC + c0 + cl)*TV + r];
            }
        } else {
            #pragma unroll
            for (int it = 0; it < 8; ++it) {
                int lin = it * 256 + tid;
                int cl = lin & 31, pl = lin >> 5;
                A_s[pl*33 + cl] = A[(p0 + pl)*256 + c0 + cl];
            }
        }
        // ---- load W tile (32 k x 256 cols) ----
        #pragma unroll
        for (int it = 0; it < 32; ++it) {
            int lin = it * 256 + tid;
            if constexpr (MODE == 2 || MODE == 3) {
                int cl = lin & 31, j = lin >> 5;              // W is (out,in)
                W_s[cl*260 + j] = Wm[j*256 + c0 + cl];
            } else {
                int j = lin & 255, cl = lin >> 8;             // W is (in,out)
                int ldw = (MODE == 0) ? 768 : 256;
                W_s[cl*260 + j] = Wm[(c0 + cl)*ldw + jb + j];
            }
        }
        __syncthreads();
        // ---- 8x8 microtile FMA ----
        #pragma unroll 8
        for (int c = 0; c < 32; ++c) {
            float a[8], w[8];
            #pragma unroll
            for (int i = 0; i < 8; ++i) a[i] = A_s[(pg*8 + i)*33 + c];
            *(float4*)&w[0] = *(const float4*)&W_s[c*260 + cg*8];
            *(float4*)&w[4] = *(const float4*)&W_s[c*260 + cg*8 + 4];
            #pragma unroll
            for (int i = 0; i < 8; ++i)
                #pragma unroll
                for (int j = 0; j < 8; ++j)
                    acc[i][j] = fmaf(a[i], w[j], acc[i][j]);
        }
        __syncthreads();
    }

    // ---- epilogues ----
    if constexpr (MODE == 0) {
        #pragma unroll
        for (int i = 0; i < 8; ++i) {
            int p = p0 + pg*8 + i;
            *(float4*)&g_qkv[p*768 + jb + cg*8]     = *(float4*)&acc[i][0];
            *(float4*)&g_qkv[p*768 + jb + cg*8 + 4] = *(float4*)&acc[i][4];
        }
    } else if constexpr (MODE == 1) {
        float sc[8], be[8], bo[8];
        #pragma unroll
        for (int jj = 0; jj < 8; ++jj) {
            int j = cg*8 + jj;
            sc[jj] = rsqrtf(bv[j] + EPSV) * bg[j];
            be[jj] = bb[j] - bm[j]*sc[jj];
            bo[jj] = bias[j];
        }
        #pragma unroll
        for (int i = 0; i < 8; ++i) {
            int p = p0 + pg*8 + i;
            int n = p / TV, r = p - n * TV;
            float vals[8];
            #pragma unroll
            for (int jj = 0; jj < 8; ++jj) {
                int j = cg*8 + jj;
                float xr = res[(n*CC + j)*TV + r];
                vals[jj] = (acc[i][jj] + bo[jj] + xr)*sc[jj] + be[jj];
            }
            *(float4*)&g_inter[p*256 + cg*8]     = *(float4*)&vals[0];
            *(float4*)&g_inter[p*256 + cg*8 + 4] = *(float4*)&vals[4];
        }
    } else if constexpr (MODE == 2) {
        float sc[8], be[8];
        #pragma unroll
        for (int jj = 0; jj < 8; ++jj) {
            int j = cg*8 + jj;
            sc[jj] = rsqrtf(bv[j] + EPSV) * bg[j];
            be[jj] = bb[j] - bm[j]*sc[jj];
        }
        #pragma unroll
        for (int i = 0; i < 8; ++i) {
            int p = p0 + pg*8 + i;
            float vals[8];
            #pragma unroll
            for (int jj = 0; jj < 8; ++jj) {
                float a = acc[i][jj];
                float sp = (a > 20.f) ? a : log1pf(__expf(a));
                float ms = a * tanhf(sp);
                vals[jj] = ms*sc[jj] + be[jj];
            }
            *(float4*)&g_h1[p*256 + cg*8]     = *(float4*)&vals[0];
            *(float4*)&g_h1[p*256 + cg*8 + 4] = *(float4*)&vals[4];
        }
    } else {
        float sc[8], be[8];
        #pragma unroll
        for (int jj = 0; jj < 8; ++jj) {
            int j = cg*8 + jj;
            sc[jj] = rsqrtf(bv[j] + EPSV) * bg[j];
            be[jj] = bb[j] - bm[j]*sc[jj];
        }
        #pragma unroll
        for (int i = 0; i < 8; ++i) {
            int p = p0 + pg*8 + i;
            int n = p / TV, r = p - n * TV;
            float rv[8];
            *(float4*)&rv[0] = *(const float4*)&g_inter[p*256 + cg*8];
            *(float4*)&rv[4] = *(const float4*)&g_inter[p*256 + cg*8 + 4];
            #pragma unroll
            for (int jj = 0; jj < 8; ++jj) {
                int j = cg*8 + jj;
                float val = (acc[i][jj] + rv[jj])*sc[jj] + be[jj];
                outp[(n*CC + j)*TV + r] = val;
            }
        }
    }
}

// ---------------------------------------------------------------------------
// Attention: one block per (n*T + t, head). Gathers 125 window rows (zero
// padded to 128), S = Q K^T / 16, softmax (norm folded into O), O = S V,
// mean over the 5 window slots, writes g_ao.
// ---------------------------------------------------------------------------
#define SM_S    0                       // S[l*132 + m]        128*132 = 16896
#define SM_K    16896                   // ks_t[d*132 + m]     32*132  = 4224
#define SM_Q    21120                   // qs_t[d*132 + m]     4224
#define SM_V    25344                   // vs[m*36 + d]        128*36  = 4608
#define SM_SUM  29952                   // sums[128]
#define SM_O    16896                   // O_s[l*36 + d] overlays ks_t/qs_t
#define ATTN_SMEM_FLOATS 30080

__global__ __launch_bounds__(256)
void attn_kernel()
{
    extern __shared__ float sm[];
    float* S    = sm + SM_S;
    float* ks_t = sm + SM_K;
    float* qs_t = sm + SM_Q;
    float* vs   = sm + SM_V;
    float* sums = sm + SM_SUM;
    float* O_s  = sm + SM_O;

    const int tid = threadIdx.x;
    const int bx = blockIdx.x, h = blockIdx.y;
    const int n = bx / TT, t = bx - n * TT;

    // gather q/k/v (zero pad out-of-range times and rows 125..127)
    for (int lin = tid; lin < 4096; lin += 256) {
        int m = lin >> 5, d = lin & 31;
        float q = 0.f, k = 0.f, v = 0.f;
        if (m < LLN) {
            int w = m / VVC;
            int vv = m - w * VVC;
            int ti = t + w - 2;
            if (ti >= 0 && ti < TT) {
                const float* bp = &g_qkv[((size_t)((n*TT + ti)*VVC + vv))*768 + h*96 + d];
                q = bp[0]; k = bp[32]; v = bp[64];
            }
        }
        qs_t[d*132 + m] = q;
        ks_t[d*132 + m] = k;
        vs[m*36 + d]    = v;
    }
    if (tid >= 125 && tid < 128) sums[tid] = 1.f;
    __syncthreads();

    // S = Q K^T * (1/16), 16x16 thread grid, 8x8 microtiles
    {
        const int ty = tid >> 4, tx = tid & 15;
        float acc[8][8];
        #pragma unroll
        for (int i = 0; i < 8; ++i)
            #pragma unroll
            for (int j = 0; j < 8; ++j) acc[i][j] = 0.f;
        #pragma unroll 8
        for (int d = 0; d < 32; ++d) {
            float a[8], b[8];
            *(float4*)&a[0] = *(const float4*)&qs_t[d*132 + ty*8];
            *(float4*)&a[4] = *(const float4*)&qs_t[d*132 + ty*8 + 4];
            *(float4*)&b[0] = *(const float4*)&ks_t[d*132 + tx*8];
            *(float4*)&b[4] = *(const float4*)&ks_t[d*132 + tx*8 + 4];
            #pragma unroll
            for (int i = 0; i < 8; ++i)
                #pragma unroll
                for (int j = 0; j < 8; ++j)
                    acc[i][j] = fmaf(a[i], b[j], acc[i][j]);
        }
        #pragma unroll
        for (int i = 0; i < 8; ++i) {
            float tmp[8];
            #pragma unroll
            for (int j = 0; j < 8; ++j) tmp[j] = acc[i][j] * 0.0625f;
            *(float4*)&S[(ty*8 + i)*132 + tx*8]     = *(float4*)&tmp[0];
            *(float4*)&S[(ty*8 + i)*132 + tx*8 + 4] = *(float4*)&tmp[4];
        }
    }
    __syncthreads();

    // softmax per row l (normalization deferred via sums)
    if (tid < LLN) {
        const int l = tid;
        float mx = -1e30f;
        for (int m = 0; m < LLN; ++m) mx = fmaxf(mx, S[l*132 + m]);
        float s = 0.f;
        for (int m = 0; m < LLN; ++m) {
            float e = __expf(S[l*132 + m] - mx);
            S[l*132 + m] = e;
            s += e;
        }
        sums[l] = s;
    }
    __syncthreads();

    // O = S V, 32x8 thread grid, 4l x 4d microtiles; divide by sums
    {
        const int ty2 = tid >> 3, tx2 = tid & 7;
        float acc[4][4];
        #pragma unroll
        for (int i = 0; i < 4; ++i)
            #pragma unroll
            for (int j = 0; j < 4; ++j) acc[i][j] = 0.f;
        #pragma unroll 5
        for (int m = 0; m < LLN; ++m) {
            float a[4], b[4];
            #pragma unroll
            for (int i = 0; i < 4; ++i) a[i] = S[(ty2*4 + i)*132 + m];
            *(float4*)&b[0] = *(const float4*)&vs[m*36 + tx2*4];
            #pragma unroll
            for (int i = 0; i < 4; ++i)
                #pragma unroll
                for (int j = 0; j < 4; ++j)
                    acc[i][j] = fmaf(a[i], b[j], acc[i][j]);
        }
        #pragma unroll
        for (int i = 0; i < 4; ++i) {
            int l = ty2*4 + i;
            float rl = 1.f / sums[l];
            float tmp[4];
            #pragma unroll
            for (int j = 0; j < 4; ++j) tmp[j] = acc[i][j] * rl;
            *(float4*)&O_s[l*36 + tx2*4] = *(float4*)&tmp[0];
        }
    }
    __syncthreads();

    // mean over the 5 window slots -> g_ao
    for (int lin = tid; lin < 800; lin += 256) {
        int vv = lin >> 5, d = lin & 31;
        float s = 0.f;
        #pragma unroll
        for (int w = 0; w < 5; ++w) s += O_s[(w*VVC + vv)*36 + d];
        g_ao[((size_t)((n*TT + t)*VVC + vv))*256 + h*HD + d] = 0.2f * s;
    }
}

// ---------------------------------------------------------------------------
extern "C" void kernel_launch(void* const* d_in, const int* in_sizes, int n_in,
                              void* d_out, int out_size)
{
    const float* x      = (const float*)d_in[0];
    const float* w_qkv  = (const float*)d_in[1];
    const float* w_out  = (const float*)d_in[2];
    const float* b_out  = (const float*)d_in[3];
    const float* bn1_g  = (const float*)d_in[4];
    const float* bn1_b  = (const float*)d_in[5];
    const float* ffn_w1 = (const float*)d_in[6];
    const float* ffn_w2 = (const float*)d_in[7];
    const float* ffn_g  = (const float*)d_in[8];
    const float* ffn_b  = (const float*)d_in[9];
    const float* bn2_g  = (const float*)d_in[10];
    const float* bn2_b  = (const float*)d_in[11];
    const float* bn1_m  = (const float*)d_in[12];
    const float* bn1_v  = (const float*)d_in[13];
    const float* ffn_m  = (const float*)d_in[14];
    const float* ffn_v  = (const float*)d_in[15];
    const float* bn2_m  = (const float*)d_in[16];
    const float* bn2_v  = (const float*)d_in[17];
    float* out = (float*)d_out;

    cudaFuncSetAttribute(attn_kernel,
                         cudaFuncAttributeMaxDynamicSharedMemorySize,
                         ATTN_SMEM_FLOATS * 4);

    // K1: QKV projection (all 768 cols, 3 sections via grid.y)
    gemm_kernel<0><<<dim3(PP/64, 3), 256>>>(x, w_qkv,
        nullptr, nullptr, nullptr, nullptr, nullptr, nullptr, nullptr);

    // K2: attention + mean over window slots
    attn_kernel<<<dim3(NB*TT, HH), 256, ATTN_SMEM_FLOATS * 4>>>();

    // K3: out projection + b_out + x residual + bn1 -> g_inter
    gemm_kernel<1><<<PP/64, 256>>>(nullptr, w_out,
        b_out, x, bn1_g, bn1_b, bn1_m, bn1_v, nullptr);

    // K4: ffn1 + mish + bn(ffn) -> g_h1
    gemm_kernel<2><<<PP/64, 256>>>(nullptr, ffn_w1,
        nullptr, nullptr, ffn_g, ffn_b, ffn_m, ffn_v, nullptr);

    // K5: ffn2 + residual(g_inter) + bn2 -> out (NCHW scatter)
    gemm_kernel<3><<<PP/64, 256>>>(nullptr, ffn_w2,
        nullptr, nullptr, bn2_g, bn2_b, bn2_m, bn2_v, out);
}

// round 3
// speedup vs baseline: 1.1862x; 1.1862x over previous
#include <cuda_runtime.h>
#include <cstdint>
#include <math.h>

#define NB 8
#define CC 256
#define TT 120
#define VVC 25
#define PP (NB*TT*VVC)   // 24000 points
#define TV (TT*VVC)      // 3000
#define HH 8
#define HD 32
#define LLN 125
#define EPSV 1e-5f

// Scratch (device globals; no allocation anywhere)
__device__ __align__(16) float g_qkv[PP*768];    // (p, 768) cols = h*96 + s*32 + d
__device__ __align__(16) float g_ao[PP*256];     // mean-over-W attention out, (p, h*32+d)
__device__ __align__(16) float g_inter[PP*256];  // bn1 output, point-major
__device__ __align__(16) float g_h1[PP*256];     // ffn mid, point-major

// ---------------------------------------------------------------------------
// cp.async helpers
// ---------------------------------------------------------------------------
__device__ __forceinline__ void cp16(float* dst, const float* src) {
    unsigned int d = (unsigned int)__cvta_generic_to_shared(dst);
    asm volatile("cp.async.cg.shared.global [%0], [%1], 16;\n" :: "r"(d), "l"(src));
}
__device__ __forceinline__ void cp4(float* dst, const float* src) {
    unsigned int d = (unsigned int)__cvta_generic_to_shared(dst);
    asm volatile("cp.async.ca.shared.global [%0], [%1], 4;\n" :: "r"(d), "l"(src));
}
#define CP_COMMIT() asm volatile("cp.async.commit_group;\n" ::: "memory")
#define CP_WAIT1()  asm volatile("cp.async.wait_group 1;\n" ::: "memory")
#define CP_WAIT0()  asm volatile("cp.async.wait_group 0;\n" ::: "memory")

// Shared memory sizes (floats)
#define ASTR 36
#define A_TILE (64*ASTR)          // 2304
#define WSTR_X 260
#define W_TILE_X (32*WSTR_X)      // 8320
#define WSTR_Y 36
#define W_TILE_Y (256*WSTR_Y)     // 9216
#define SMEM_X_BYTES ((2*A_TILE + 2*W_TILE_X)*4)   // 84992
#define SMEM_Y_BYTES ((2*A_TILE + 2*W_TILE_Y)*4)   // 92160

// ---------------------------------------------------------------------------
// Generic 64-point x 256-col GEMM with K=256, fused epilogues.
// MODE 0: qkv    : A = x (NCHW gather), W=(in,out) ld=768 -> g_qkv  (variant X)
// MODE 1: proj   : A = g_ao, W=w_out (in,out), epi: +b_out +x bn1 -> g_inter (X)
// MODE 2: ffn1   : A = g_inter, W=ffn_w1 (out,in), epi: mish bn -> g_h1 (variant Y)
// MODE 3: ffn2   : A = g_h1, W=ffn_w2 (out,in), epi: +g_inter bn2 -> out (Y)
// Variant X: thread cols j = cg*8+jj (contiguous 8)
// Variant Y: thread cols j = cg + jj*32 (strided) — lets W be copied untransposed
// ---------------------------------------------------------------------------
template<int MODE>
__global__ __launch_bounds__(256)
void gemm_kernel(const float* __restrict__ Aext, const float* __restrict__ Wm,
                 const float* __restrict__ bias, const float* __restrict__ res,
                 const float* __restrict__ bg, const float* __restrict__ bb,
                 const float* __restrict__ bm, const float* __restrict__ bv,
                 float* __restrict__ outp)
{
    extern __shared__ float sm[];
    float* A_s = sm;                      // [2][A_TILE]
    float* W_s = sm + 2*A_TILE;           // [2][W_TILE_X or W_TILE_Y]

    const int tid = threadIdx.x;
    const int cg = tid & 31;
    const int pg = tid >> 5;
    const int p0 = blockIdx.x * 64;
    const int jb = (MODE == 0) ? (int)blockIdx.y * 256 : 0;

    const float* A;
    if constexpr (MODE == 0) A = Aext;
    else if constexpr (MODE == 1) A = g_ao;
    else if constexpr (MODE == 2) A = g_inter;
    else A = g_h1;

    float acc[8][8];
    #pragma unroll
    for (int i = 0; i < 8; ++i)
        #pragma unroll
        for (int j = 0; j < 8; ++j) acc[i][j] = 0.f;

    // ---- async tile loader ----
    auto load_tile = [&](int kt, int buf) {
        const int c0 = kt * 32;
        float* Ab = A_s + buf * A_TILE;
        if constexpr (MODE == 0) {
            #pragma unroll
            for (int it = 0; it < 8; ++it) {
                int lin = it * 256 + tid;
                int pl = lin & 63, cl = lin >> 6;
                int p = p0 + pl;
                int n = p / TV, r = p - n * TV;
                cp4(&Ab[pl*ASTR + cl], &Aext[(n*CC + c0 + cl)*TV + r]);
            }
        } else {
            #pragma unroll
            for (int it = 0; it < 2; ++it) {
                int lin = it * 256 + tid;      // 512 float4
                int pl = lin >> 3, f = lin & 7;
                cp16(&Ab[pl*ASTR + f*4], &A[(p0 + pl)*256 + c0 + f*4]);
            }
        }
        if constexpr (MODE == 0 || MODE == 1) {
            float* Wb = W_s + buf * W_TILE_X;
            const int ldw = (MODE == 0) ? 768 : 256;
            #pragma unroll
            for (int it = 0; it < 8; ++it) {
                int lin = it * 256 + tid;      // 2048 float4 = 32 rows x 64
                int cl = lin >> 6, f = lin & 63;
                cp16(&Wb[cl*WSTR_X + f*4], &Wm[(c0 + cl)*ldw + jb + f*4]);
            }
        } else {
            float* Wb = W_s + buf * W_TILE_Y;
            #pragma unroll
            for (int it = 0; it < 8; ++it) {
                int lin = it * 256 + tid;      // 2048 float4 = 256 rows x 8
                int j = lin >> 3, f = lin & 7;
                cp16(&Wb[j*WSTR_Y + f*4], &Wm[j*256 + c0 + f*4]);
            }
        }
    };

    load_tile(0, 0);
    CP_COMMIT();

    int buf = 0;
    for (int kt = 0; kt < 8; ++kt) {
        if (kt < 7) { load_tile(kt + 1, buf ^ 1); CP_COMMIT(); CP_WAIT1(); }
        else        { CP_WAIT0(); }
        __syncthreads();

        const float* Ab = A_s + buf * A_TILE;
        if constexpr (MODE == 0 || MODE == 1) {
            const float* Wb = W_s + buf * W_TILE_X;
            #pragma unroll
            for (int c4 = 0; c4 < 8; ++c4) {
                float4 a4[8];
                #pragma unroll
                for (int i = 0; i < 8; ++i)
                    a4[i] = *(const float4*)&Ab[(pg*8 + i)*ASTR + c4*4];
                #pragma unroll
                for (int cc = 0; cc < 4; ++cc) {
                    float w[8];
                    *(float4*)&w[0] = *(const float4*)&Wb[(c4*4 + cc)*WSTR_X + cg*8];
                    *(float4*)&w[4] = *(const float4*)&Wb[(c4*4 + cc)*WSTR_X + cg*8 + 4];
                    #pragma unroll
                    for (int i = 0; i < 8; ++i) {
                        float av = (cc == 0) ? a4[i].x : (cc == 1) ? a4[i].y
                                 : (cc == 2) ? a4[i].z : a4[i].w;
                        #pragma unroll
                        for (int j = 0; j < 8; ++j)
                            acc[i][j] = fmaf(av, w[j], acc[i][j]);
                    }
                }
            }
        } else {
            const float* Wb = W_s + buf * W_TILE_Y;
            #pragma unroll
            for (int c4 = 0; c4 < 8; ++c4) {
                float4 a4[8];
                #pragma unroll
                for (int i = 0; i < 8; ++i)
                    a4[i] = *(const float4*)&Ab[(pg*8 + i)*ASTR + c4*4];
                #pragma unroll
                for (int jh = 0; jh < 2; ++jh) {
                    float4 w4[4];
                    #pragma unroll
                    for (int j = 0; j < 4; ++j)
                        w4[j] = *(const float4*)&Wb[(cg + (jh*4 + j)*32)*WSTR_Y + c4*4];
                    #pragma unroll
                    for (int i = 0; i < 8; ++i)
                        #pragma unroll
                        for (int j = 0; j < 4; ++j) {
                            int jj = jh*4 + j;
                            acc[i][jj] = fmaf(a4[i].x, w4[j].x, acc[i][jj]);
                            acc[i][jj] = fmaf(a4[i].y, w4[j].y, acc[i][jj]);
                            acc[i][jj] = fmaf(a4[i].z, w4[j].z, acc[i][jj]);
                            acc[i][jj] = fmaf(a4[i].w, w4[j].w, acc[i][jj]);
                        }
                }
            }
        }
        __syncthreads();
        buf ^= 1;
    }

    // ---- epilogues ----
    if constexpr (MODE == 0) {
        #pragma unroll
        for (int i = 0; i < 8; ++i) {
            int p = p0 + pg*8 + i;
            *(float4*)&g_qkv[p*768 + jb + cg*8]     = *(float4*)&acc[i][0];
            *(float4*)&g_qkv[p*768 + jb + cg*8 + 4] = *(float4*)&acc[i][4];
        }
    } else if constexpr (MODE == 1) {
        float sc[8], be[8], bo[8];
        #pragma unroll
        for (int jj = 0; jj < 8; ++jj) {
            int j = cg*8 + jj;
            sc[jj] = rsqrtf(bv[j] + EPSV) * bg[j];
            be[jj] = bb[j] - bm[j]*sc[jj];
            bo[jj] = bias[j];
        }
        #pragma unroll
        for (int i = 0; i < 8; ++i) {
            int p = p0 + pg*8 + i;
            int n = p / TV, r = p - n * TV;
            float vals[8];
            #pragma unroll
            for (int jj = 0; jj < 8; ++jj) {
                int j = cg*8 + jj;
                float xr = res[(n*CC + j)*TV + r];
                vals[jj] = (acc[i][jj] + bo[jj] + xr)*sc[jj] + be[jj];
            }
            *(float4*)&g_inter[p*256 + cg*8]     = *(float4*)&vals[0];
            *(float4*)&g_inter[p*256 + cg*8 + 4] = *(float4*)&vals[4];
        }
    } else if constexpr (MODE == 2) {
        float sc[8], be[8];
        #pragma unroll
        for (int jj = 0; jj < 8; ++jj) {
            int j = cg + jj*32;
            sc[jj] = rsqrtf(bv[j] + EPSV) * bg[j];
            be[jj] = bb[j] - bm[j]*sc[jj];
        }
        #pragma unroll
        for (int i = 0; i < 8; ++i) {
            int p = p0 + pg*8 + i;
            #pragma unroll
            for (int jj = 0; jj < 8; ++jj) {
                float a = acc[i][jj];
                float sp = (a > 20.f) ? a : log1pf(__expf(a));
                float ms = a * tanhf(sp);
                g_h1[p*256 + cg + jj*32] = ms*sc[jj] + be[jj];
            }
        }
    } else {
        float sc[8], be[8];
        #pragma unroll
        for (int jj = 0; jj < 8; ++jj) {
            int j = cg + jj*32;
            sc[jj] = rsqrtf(bv[j] + EPSV) * bg[j];
            be[jj] = bb[j] - bm[j]*sc[jj];
        }
        #pragma unroll
        for (int i = 0; i < 8; ++i) {
            int p = p0 + pg*8 + i;
            int n = p / TV, r = p - n * TV;
            #pragma unroll
            for (int jj = 0; jj < 8; ++jj) {
                int j = cg + jj*32;
                float rv = g_inter[p*256 + j];
                outp[(n*CC + j)*TV + r] = (acc[i][jj] + rv)*sc[jj] + be[jj];
            }
        }
    }
}

// ---------------------------------------------------------------------------
// Attention: one block per (n*T + t, head). Gathers 125 window rows (zero
// padded to 128), S = Q K^T / 16, parallel vectorized softmax (cols 125..127
// padded to -1e30 so exp = 0), O = S V over all 128, mean over window slots.
// ---------------------------------------------------------------------------
#define SM_S    0                       // S[l*132 + m]        128*132 = 16896
#define SM_K    16896                   // ks_t[d*132 + m]     32*132  = 4224
#define SM_Q    21120                   // qs_t[d*132 + m]     4224
#define SM_V    25344                   // vs[m*36 + d]        128*36  = 4608
#define SM_SUM  29952                   // sums[128]
#define SM_O    16896                   // O_s[l*36 + d] overlays ks_t/qs_t
#define ATTN_SMEM_FLOATS 30080

__global__ __launch_bounds__(256)
void attn_kernel()
{
    extern __shared__ float sm[];
    float* S    = sm + SM_S;
    float* ks_t = sm + SM_K;
    float* qs_t = sm + SM_Q;
    float* vs   = sm + SM_V;
    float* sums = sm + SM_SUM;
    float* O_s  = sm + SM_O;

    const int tid = threadIdx.x;
    const int bx = blockIdx.x, h = blockIdx.y;
    const int n = bx / TT, t = bx - n * TT;

    // gather q/k/v (zero pad out-of-range times and rows 125..127)
    for (int lin = tid; lin < 4096; lin += 256) {
        int m = lin >> 5, d = lin & 31;
        float q = 0.f, k = 0.f, v = 0.f;
        if (m < LLN) {
            int w = m / VVC;
            int vv = m - w * VVC;
            int ti = t + w - 2;
            if (ti >= 0 && ti < TT) {
                const float* bp = &g_qkv[((size_t)((n*TT + ti)*VVC + vv))*768 + h*96 + d];
                q = bp[0]; k = bp[32]; v = bp[64];
            }
        }
        qs_t[d*132 + m] = q;
        ks_t[d*132 + m] = k;
        vs[m*36 + d]    = v;
    }
    __syncthreads();

    // S = Q K^T * (1/16), 16x16 thread grid, 8x8 microtiles
    {
        const int ty = tid >> 4, tx = tid & 15;
        float acc[8][8];
        #pragma unroll
        for (int i = 0; i < 8; ++i)
            #pragma unroll
            for (int j = 0; j < 8; ++j) acc[i][j] = 0.f;
        #pragma unroll 8
        for (int d = 0; d < 32; ++d) {
            float a[8], b[8];
            *(float4*)&a[0] = *(const float4*)&qs_t[d*132 + ty*8];
            *(float4*)&a[4] = *(const float4*)&qs_t[d*132 + ty*8 + 4];
            *(float4*)&b[0] = *(const float4*)&ks_t[d*132 + tx*8];
            *(float4*)&b[4] = *(const float4*)&ks_t[d*132 + tx*8 + 4];
            #pragma unroll
            for (int i = 0; i < 8; ++i)
                #pragma unroll
                for (int j = 0; j < 8; ++j)
                    acc[i][j] = fmaf(a[i], b[j], acc[i][j]);
        }
        #pragma unroll
        for (int i = 0; i < 8; ++i) {
            float tmp[8];
            #pragma unroll
            for (int j = 0; j < 8; ++j) tmp[j] = acc[i][j] * 0.0625f;
            if (tx == 15) { tmp[5] = -1e30f; tmp[6] = -1e30f; tmp[7] = -1e30f; }
            *(float4*)&S[(ty*8 + i)*132 + tx*8]     = *(float4*)&tmp[0];
            *(float4*)&S[(ty*8 + i)*132 + tx*8 + 4] = *(float4*)&tmp[4];
        }
    }
    __syncthreads();

    // parallel softmax: one thread per row, float4 passes (conflict-free:
    // row stride 132 floats = 33 float4 -> perfect phase spread)
    if (tid < 128) {
        const int l = tid;
        float4* row = (float4*)&S[l*132];
        float mx = -1e30f;
        #pragma unroll
        for (int i = 0; i < 32; ++i) {
            float4 f = row[i];
            mx = fmaxf(mx, fmaxf(fmaxf(f.x, f.y), fmaxf(f.z, f.w)));
        }
        float s = 0.f;
        #pragma unroll
        for (int i = 0; i < 32; ++i) {
            float4 f = row[i];
            f.x = __expf(f.x - mx); f.y = __expf(f.y - mx);
            f.z = __expf(f.z - mx); f.w = __expf(f.w - mx);
            s += f.x + f.y + f.z + f.w;
            row[i] = f;
        }
        sums[l] = s;
    }
    __syncthreads();

    // O = S V over all 128 m (padded exp = 0, padded v = 0), divide by sums
    {
        const int ty2 = tid >> 3, tx2 = tid & 7;
        float acc[4][4];
        #pragma unroll
        for (int i = 0; i < 4; ++i)
            #pragma unroll
            for (int j = 0; j < 4; ++j) acc[i][j] = 0.f;
        #pragma unroll 8
        for (int m = 0; m < 128; ++m) {
            float a[4], b[4];
            #pragma unroll
            for (int i = 0; i < 4; ++i) a[i] = S[(ty2*4 + i)*132 + m];
            *(float4*)&b[0] = *(const float4*)&vs[m*36 + tx2*4];
            #pragma unroll
            for (int i = 0; i < 4; ++i)
                #pragma unroll
                for (int j = 0; j < 4; ++j)
                    acc[i][j] = fmaf(a[i], b[j], acc[i][j]);
        }
        #pragma unroll
        for (int i = 0; i < 4; ++i) {
            int l = ty2*4 + i;
            float rl = 1.f / sums[l];
            float tmp[4];
            #pragma unroll
            for (int j = 0; j < 4; ++j) tmp[j] = acc[i][j] * rl;
            *(float4*)&O_s[l*36 + tx2*4] = *(float4*)&tmp[0];
        }
    }
    __syncthreads();

    // mean over the 5 window slots -> g_ao
    for (int lin = tid; lin < 800; lin += 256) {
        int vv = lin >> 5, d = lin & 31;
        float s = 0.f;
        #pragma unroll
        for (int w = 0; w < 5; ++w) s += O_s[(w*VVC + vv)*36 + d];
        g_ao[((size_t)((n*TT + t)*VVC + vv))*256 + h*HD + d] = 0.2f * s;
    }
}

// ---------------------------------------------------------------------------
extern "C" void kernel_launch(void* const* d_in, const int* in_sizes, int n_in,
                              void* d_out, int out_size)
{
    const float* x      = (const float*)d_in[0];
    const float* w_qkv  = (const float*)d_in[1];
    const float* w_out  = (const float*)d_in[2];
    const float* b_out  = (const float*)d_in[3];
    const float* bn1_g  = (const float*)d_in[4];
    const float* bn1_b  = (const float*)d_in[5];
    const float* ffn_w1 = (const float*)d_in[6];
    const float* ffn_w2 = (const float*)d_in[7];
    const float* ffn_g  = (const float*)d_in[8];
    const float* ffn_b  = (const float*)d_in[9];
    const float* bn2_g  = (const float*)d_in[10];
    const float* bn2_b  = (const float*)d_in[11];
    const float* bn1_m  = (const float*)d_in[12];
    const float* bn1_v  = (const float*)d_in[13];
    const float* ffn_m  = (const float*)d_in[14];
    const float* ffn_v  = (const float*)d_in[15];
    const float* bn2_m  = (const float*)d_in[16];
    const float* bn2_v  = (const float*)d_in[17];
    float* out = (float*)d_out;

    static int attr_done = 0;
    if (!attr_done) {
        cudaFuncSetAttribute(attn_kernel,
            cudaFuncAttributeMaxDynamicSharedMemorySize, ATTN_SMEM_FLOATS * 4);
        cudaFuncSetAttribute(gemm_kernel<0>,
            cudaFuncAttributeMaxDynamicSharedMemorySize, SMEM_X_BYTES);
        cudaFuncSetAttribute(gemm_kernel<1>,
            cudaFuncAttributeMaxDynamicSharedMemorySize, SMEM_X_BYTES);
        cudaFuncSetAttribute(gemm_kernel<2>,
            cudaFuncAttributeMaxDynamicSharedMemorySize, SMEM_Y_BYTES);
        cudaFuncSetAttribute(gemm_kernel<3>,
            cudaFuncAttributeMaxDynamicSharedMemorySize, SMEM_Y_BYTES);
        attr_done = 1;
    }

    // K1: QKV projection (all 768 cols, 3 sections via grid.y)
    gemm_kernel<0><<<dim3(PP/64, 3), 256, SMEM_X_BYTES>>>(x, w_qkv,
        nullptr, nullptr, nullptr, nullptr, nullptr, nullptr, nullptr);

    // K2: attention + mean over window slots
    attn_kernel<<<dim3(NB*TT, HH), 256, ATTN_SMEM_FLOATS * 4>>>();

    // K3: out projection + b_out + x residual + bn1 -> g_inter
    gemm_kernel<1><<<PP/64, 256, SMEM_X_BYTES>>>(nullptr, w_out,
        b_out, x, bn1_g, bn1_b, bn1_m, bn1_v, nullptr);

    // K4: ffn1 + mish + bn(ffn) -> g_h1
    gemm_kernel<2><<<PP/64, 256, SMEM_Y_BYTES>>>(nullptr, ffn_w1,
        nullptr, nullptr, ffn_g, ffn_b, ffn_m, ffn_v, nullptr);

    // K5: ffn2 + residual(g_inter) + bn2 -> out (NCHW scatter)
    gemm_kernel<3><<<PP/64, 256, SMEM_Y_BYTES>>>(nullptr, ffn_w2,
        nullptr, nullptr, bn2_g, bn2_b, bn2_m, bn2_v, out);
}